// round 3
// baseline (speedup 1.0000x reference)
#include <cuda_runtime.h>
#include <math.h>

#define NMODES   6400
#define MDIM     80
#define NCHUNK   128
#define CHUNK    (NMODES / NCHUNK)      /* 50 modes per thread = 25 pairs */
#define NPAIR    (CHUNK / 2)
#define MAX_T    24576
#define TW       16                      /* samples per thread, stride 32 */
#define WTILE    (32 * TW)               /* 512 samples per warp tile */

#define KF   ((float)(1.0 / 44100.0))
#define K2F  ((float)((1.0/44100.0)*(1.0/44100.0)))

typedef unsigned long long ull;

// per-mode: g_I1[m] = {theta, sigma, coefC, rho32}
__device__ float4   g_I1[NMODES];
// per-pair (float4 view): {c32_e, s32_e, c32_o, s32_o}
__device__ float    g_ROT[NMODES * 2];
// per-pair (float4 view): {a_e, a_o, b_e, b_o}
__device__ float    g_AB[NMODES * 2];
__device__ float    g_part[NCHUNK][MAX_T];
__device__ float    g_ir[MAX_T];
__device__ unsigned g_maxbits;

// ---------------- packed f32x2 helpers (Blackwell FFMA2 path) --------------
__device__ __forceinline__ ull pk2(float lo, float hi) {
    ull r; asm("mov.b64 %0, {%1,%2};" : "=l"(r) : "f"(lo), "f"(hi)); return r;
}
__device__ __forceinline__ void upk2(ull v, float& lo, float& hi) {
    asm("mov.b64 {%0,%1}, %2;" : "=f"(lo), "=f"(hi) : "l"(v));
}
__device__ __forceinline__ ull fma2(ull a, ull b, ull c) {
    ull d; asm("fma.rn.f32x2 %0, %1, %2, %3;" : "=l"(d) : "l"(a), "l"(b), "l"(c)); return d;
}
__device__ __forceinline__ ull mul2(ull a, ull b) {
    ull d; asm("mul.rn.f32x2 %0, %1, %2;" : "=l"(d) : "l"(a), "l"(b)); return d;
}
__device__ __forceinline__ ull add2(ull a, ull b) {
    ull d; asm("add.rn.f32x2 %0, %1, %2;" : "=l"(d) : "l"(a), "l"(b)); return d;
}

// ---------------------------------------------------------------------------
// Accurate flag-proof sine / sincos. Cody-Waite 3-term reduction (exact for
// |n| < 2^15), deg-9/deg-8 minimax polys. Abs err ~1.5e-7.
// ---------------------------------------------------------------------------
__device__ __forceinline__ float sin_acc(float x) {
    const float INV_PI = 0.318309886183790671538f;
    float nf = rintf(__fmul_rn(x, INV_PI));
    int   ni = (int)nf;
    float r = __fmaf_rn(-nf, 3.140625f, x);
    r = __fmaf_rn(-nf, 9.670257568359375e-4f, r);
    r = __fmaf_rn(-nf, 6.2771141529083252e-7f, r);
    float r2 = __fmul_rn(r, r);
    float p  = __fmaf_rn(2.60831598097865935e-06f, r2, -1.98106907191686332e-4f);
    p = __fmaf_rn(p, r2,  8.33307858556509018e-3f);
    p = __fmaf_rn(p, r2, -0.166666597127914429f);
    float s = __fmaf_rn(__fmul_rn(r, r2), p, r);
    return __int_as_float(__float_as_int(s) ^ ((ni & 1) << 31));
}

__device__ __forceinline__ void sincos_acc(float x, float& so, float& co) {
    const float INV_PI = 0.318309886183790671538f;
    float nf = rintf(__fmul_rn(x, INV_PI));
    int   sgn = ((int)nf & 1) << 31;
    float r = __fmaf_rn(-nf, 3.140625f, x);
    r = __fmaf_rn(-nf, 9.670257568359375e-4f, r);
    r = __fmaf_rn(-nf, 6.2771141529083252e-7f, r);
    float r2 = __fmul_rn(r, r);
    float ps = __fmaf_rn(2.60831598097865935e-06f, r2, -1.98106907191686332e-4f);
    ps = __fmaf_rn(ps, r2,  8.33307858556509018e-3f);
    ps = __fmaf_rn(ps, r2, -0.166666597127914429f);
    float s = __fmaf_rn(__fmul_rn(r, r2), ps, r);
    float pc = __fmaf_rn(2.44331571e-5f, r2, -1.38873162e-3f);
    pc = __fmaf_rn(pc, r2, 4.16666456e-2f);
    pc = __fmaf_rn(pc, r2, -0.5f);
    float c = __fmaf_rn(pc, r2, 1.0f);
    so = __int_as_float(__float_as_int(s) ^ sgn);
    co = __int_as_float(__float_as_int(c) ^ sgn);
}

__device__ __forceinline__ double softplus_d(double x) {
    return (x > 0.0) ? x + log1p(exp(-x)) : log1p(exp(x));
}
__device__ __forceinline__ float sigmoid_of(float argf) {
    return (float)(1.0 / (1.0 + exp(-(double)argf)));
}

// ---------------------------------------------------------------------------
// k0: per-mode setup. Phase-critical chain in explicit f32 RN; recurrence &
// rotation coefficients in double.
// ---------------------------------------------------------------------------
__global__ void k0_setup(const float* __restrict__ mu_raw,
                         const float* __restrict__ D_raw,
                         const float* __restrict__ T0_raw,
                         const float* __restrict__ Ly_raw,
                         const float* __restrict__ xo_raw,
                         const float* __restrict__ yo_raw) {
    int m = blockIdx.x * blockDim.x + threadIdx.x;
    if (m == 0) g_maxbits = 0u;
    if (m >= NMODES) return;

    float mu  = __fadd_rn((float)softplus_d((double)*mu_raw),  1e-4f);
    float Dm  = __fadd_rn((float)softplus_d((double)*D_raw),   1e-4f);
    float T0m = __fadd_rn((float)softplus_d((double)*T0_raw),  1e-4f);

    float hLy = __fmul_rn(__fadd_rn((float)tanh((double)*Ly_raw), 1.0f), 0.5f);
    float Ly  = __fadd_rn(1.1f, __fmul_rn(2.9f, hLy));
    float hx  = __fmul_rn(__fadd_rn((float)tanh((double)*xo_raw), 1.0f), 0.5f);
    float xo  = __fadd_rn(0.49f, __fmul_rn(0.51f, hx));
    float hy  = __fmul_rn(__fadd_rn((float)tanh((double)*yo_raw), 1.0f), 0.5f);
    float yo  = __fadd_rn(__fmul_rn(0.51f, Ly), __fmul_rn(__fmul_rn(0.49f, Ly), hy));
    float yi  = __fmul_rn(0.467f, Ly);

    int mi = m / MDIM + 1;
    int nj = m % MDIM + 1;
    const float PIf = (float)M_PI;

    float mf = (float)mi, nf = (float)nj;
    float t1 = __fmul_rn(mf, PIf);
    float t2 = __fdiv_rn(__fmul_rn(nf, PIf), Ly);
    float g1 = __fadd_rn(__fmul_rn(t1, t1), __fmul_rn(t2, t2));
    float om_sq = __fadd_rn(__fmul_rn(T0m, g1),
                            __fmul_rn(__fmul_rn(Dm, g1), g1));
    float omega = __fsqrt_rn(fmaxf(om_sq, 0.0f));
    float theta = __fmul_rn(omega, KF);

    const double OM2d   = 2.0 * M_PI * 500.0;
    const double DOMSQd = OM2d * OM2d;
    const double ALPHAd = 3.0 * log(10.0) / DOMSQd * (DOMSQd / 6.0);
    const double BETAd  = 3.0 * log(10.0) / DOMSQd * (1.0 / 2.0 - 1.0 / 6.0);
    float om2f  = __fmul_rn(omega, omega);
    float sigma = __fadd_rn((float)ALPHAd, __fmul_rn((float)BETAd, om2f));

    const float MAXOMf = (float)(10000.0 * 2.0 * M_PI);
    const float LOWOMf = (float)(20.0 * 2.0 * M_PI);
    float a1 = __fdiv_rn(__fsub_rn(MAXOMf, omega), 100.0f);
    float a2 = __fdiv_rn(__fsub_rn(omega, LOWOMf), 100.0f);
    float valid = __fmul_rn(sigmoid_of(a1), sigmoid_of(a2));

    double PId = (double)PIf;
    float inw = __fmul_rn((float)cos(0.335 * PId * (double)mi),
                          (float)cos((double)yi * PId * (double)nj / (double)Ly));
    float outw = __fmul_rn((float)cos((double)xo * PId * (double)mi),
                           (float)cos((double)yo * PId * (double)nj / (double)Ly));

    float ms = __fmul_rn(__fmul_rn(0.25f, mu), Ly);
    float E  = (float)exp(-(double)__fmul_rn(sigma, KF));
    float P  = __fmul_rn(outw, inw);
    P = __fmul_rn(P, K2F);
    P = __fmul_rn(P, E);
    P = __fdiv_rn(P, ms);
    P = __fmul_rn(P, valid);

    float coef = __fdiv_rn(P, __fadd_rn(sin_acc(theta), 1e-8f));

    // stride-32 recurrence + rotation coefficients (double)
    double sd   = (double)sigma;
    double Kd   = 1.0 / 44100.0;
    double r32d = exp(-32.0 * sd * Kd);
    double Thd  = 32.0 * (double)theta;
    double c32d = cos(Thd), s32d = sin(Thd);
    float  a    = (float)(2.0 * r32d * c32d);
    float  b    = (float)(-(r32d * r32d));

    g_I1[m] = make_float4(theta, sigma, coef, (float)r32d);

    int pr = m >> 1, half = m & 1;
    g_ROT[pr * 4 + half * 2 + 0] = (float)c32d;
    g_ROT[pr * 4 + half * 2 + 1] = (float)s32d;
    g_AB [pr * 4 + half]         = a;
    g_AB [pr * 4 + 2 + half]     = b;
}

// ---------------------------------------------------------------------------
// k1: modal bank. Thread owns samples {base + 32j, j<16}; processes modes in
// PAIRS with packed f32x2 recurrence (3 packed ops / 2 mode-samples).
// Exact per-tile re-init: one accurate sincos + exact rotation by 32*theta.
// Params software-pipelined (prefetch next pair).
// ---------------------------------------------------------------------------
__global__ void __launch_bounds__(256) k1_bank(int T) {
    int gtid   = blockIdx.x * blockDim.x + threadIdx.x;
    int warp_t = gtid >> 5;
    int lane   = threadIdx.x & 31;
    int base   = warp_t * WTILE + lane;
    if (base >= T) return;
    int c = blockIdx.y;

    ull acc[TW];
#pragma unroll
    for (int j = 0; j < TW; ++j) acc[j] = 0ull;

    float tp0 = (float)(base + 1);
    float nk0 = __fmul_rn((float)base, KF);

    int m0 = c * CHUNK;
    int pr0 = m0 >> 1;
    const float4* ROT4 = (const float4*)g_ROT;
    const float4* AB4  = (const float4*)g_AB;

    // prefetch pair 0
    float4 nI1e = g_I1[m0];
    float4 nI1o = g_I1[m0 + 1];
    float4 nROT = ROT4[pr0];
    float4 nAB  = AB4[pr0];

    for (int q = 0; q < NPAIR; ++q) {
        float4 i1e = nI1e, i1o = nI1o, rot = nROT, ab = nAB;
        if (q + 1 < NPAIR) {
            int mq = m0 + 2 * (q + 1);
            nI1e = g_I1[mq];
            nI1o = g_I1[mq + 1];
            nROT = ROT4[pr0 + q + 1];
            nAB  = AB4[pr0 + q + 1];
        }

        // ---- scalar init, even mode ----
        float s0e, c0e;
        sincos_acc(__fmul_rn(tp0, i1e.x), s0e, c0e);
        float s1e = __fmaf_rn(s0e, rot.x, __fmul_rn(c0e, rot.y));
        float we  = __fmul_rn(i1e.z, __expf(-__fmul_rn(i1e.y, nk0)));
        float v0e = __fmul_rn(we, s0e);
        float v1e = __fmul_rn(__fmul_rn(we, i1e.w), s1e);

        // ---- scalar init, odd mode ----
        float s0o, c0o;
        sincos_acc(__fmul_rn(tp0, i1o.x), s0o, c0o);
        float s1o = __fmaf_rn(s0o, rot.z, __fmul_rn(c0o, rot.w));
        float wo  = __fmul_rn(i1o.z, __expf(-__fmul_rn(i1o.y, nk0)));
        float v0o = __fmul_rn(wo, s0o);
        float v1o = __fmul_rn(__fmul_rn(wo, i1o.w), s1o);

        ull V0 = pk2(v0e, v0o);
        ull V1 = pk2(v1e, v1o);
        ull A  = pk2(ab.x, ab.y);
        ull B  = pk2(ab.z, ab.w);

        acc[0] = add2(acc[0], V0);
        acc[1] = add2(acc[1], V1);
#pragma unroll
        for (int j = 2; j < TW; ++j) {
            ull V2 = fma2(A, V1, mul2(B, V0));
            acc[j] = add2(acc[j], V2);
            V0 = V1; V1 = V2;
        }
    }

#pragma unroll
    for (int j = 0; j < TW; ++j) {
        int t = base + 32 * j;
        if (t < T) {
            float x, y; upk2(acc[j], x, y);
            g_part[c][t] = __fadd_rn(x, y);
        }
    }
}

// ---------------------------------------------------------------------------
// k2: sum chunks, first difference / K, track max|ir|
// ---------------------------------------------------------------------------
__global__ void k2_diff(int T) {
    __shared__ float sm[257];
    int t = blockIdx.x * blockDim.x + threadIdx.x;

    float s = 0.0f;
    if (t < T) {
#pragma unroll 8
        for (int c = 0; c < NCHUNK; ++c) s += g_part[c][t];
    }
    sm[threadIdx.x + 1] = s;
    if (threadIdx.x == 0) {
        float p = 0.0f;
        int tp = (int)(blockIdx.x * blockDim.x) - 1;
        if (tp >= 0 && tp < T) {
            for (int c = 0; c < NCHUNK; ++c) p += g_part[c][tp];
        }
        sm[0] = p;
    }
    __syncthreads();
    if (t >= T) return;

    float prev = (t == 0) ? 0.0f : sm[threadIdx.x];
    float ir = __fdiv_rn(__fsub_rn(s, prev), KF);
    g_ir[t] = ir;
    atomicMax(&g_maxbits, __float_as_uint(fabsf(ir)));
}

// ---------------------------------------------------------------------------
// k3: peak normalize
// ---------------------------------------------------------------------------
__global__ void k3_norm(int T, float* __restrict__ out) {
    int t = blockIdx.x * blockDim.x + threadIdx.x;
    if (t >= T) return;
    float mx = __uint_as_float(g_maxbits);
    out[t] = __fdiv_rn(g_ir[t], __fadd_rn(mx, 1e-8f));
}

// ---------------------------------------------------------------------------
extern "C" void kernel_launch(void* const* d_in, const int* in_sizes, int n_in,
                              void* d_out, int out_size) {
    (void)in_sizes; (void)n_in;
    const float* mu   = (const float*)d_in[0];
    const float* Dr   = (const float*)d_in[1];
    const float* T0r  = (const float*)d_in[2];
    const float* Lyr  = (const float*)d_in[3];
    const float* xor_ = (const float*)d_in[4];
    const float* yor_ = (const float*)d_in[5];

    int T = out_size;
    if (T > MAX_T) T = MAX_T;

    k0_setup<<<NMODES / 256, 256>>>(mu, Dr, T0r, Lyr, xor_, yor_);

    int warps_t  = (T + WTILE - 1) / WTILE;
    int blocks_x = (warps_t + 7) / 8;
    dim3 g1(blocks_x, NCHUNK);
    k1_bank<<<g1, 256>>>(T);

    int gb = (T + 255) / 256;
    k2_diff<<<gb, 256>>>(T);
    k3_norm<<<gb, 256>>>(T, (float*)d_out);
}

// round 4
// speedup vs baseline: 1.2196x; 1.2196x over previous
#include <cuda_runtime.h>
#include <math.h>

#define NMODES   6400
#define MDIM     80
#define NCHUNK   128
#define CHUNK    (NMODES / NCHUNK)      /* 50 modes per chunk */
#define MAX_T    24576
#define TW       32                      /* samples per thread, stride 32 */
#define SPAN     1024                    /* samples per warp tile */
#define WPB      4                       /* warps per block in k1 */

#define KF   ((float)(1.0 / 44100.0))
#define K2F  ((float)((1.0/44100.0)*(1.0/44100.0)))

// per-mode tables
__device__ float4   g_P0[NMODES];   // {theta, sigma, C, a}
__device__ float4   g_P1[NMODES];   // {b, z1c, z1s, Z16c}
__device__ float    g_P2[NMODES];   // {Z16s}
__device__ float    g_part[NCHUNK][MAX_T];
__device__ float    g_ir[MAX_T];
__device__ unsigned g_maxbits;

// ---------------------------------------------------------------------------
// Accurate flag-proof sine / sincos. Cody-Waite 3-term reduction (exact for
// |n| < 2^15), minimax polys. Abs err ~1e-7 + n*1.2e-10 reduction tail.
// ---------------------------------------------------------------------------
__device__ __forceinline__ float sin_acc(float x) {
    const float INV_PI = 0.318309886183790671538f;
    float nf = rintf(__fmul_rn(x, INV_PI));
    int   ni = (int)nf;
    float r = __fmaf_rn(-nf, 3.140625f, x);
    r = __fmaf_rn(-nf, 9.670257568359375e-4f, r);
    r = __fmaf_rn(-nf, 6.2771141529083252e-7f, r);
    float r2 = __fmul_rn(r, r);
    float p  = __fmaf_rn(2.60831598097865935e-06f, r2, -1.98106907191686332e-4f);
    p = __fmaf_rn(p, r2,  8.33307858556509018e-3f);
    p = __fmaf_rn(p, r2, -0.166666597127914429f);
    float s = __fmaf_rn(__fmul_rn(r, r2), p, r);
    return __int_as_float(__float_as_int(s) ^ ((ni & 1) << 31));
}

__device__ __forceinline__ void sincos_acc(float x, float& so, float& co) {
    const float INV_PI = 0.318309886183790671538f;
    float nf = rintf(__fmul_rn(x, INV_PI));
    int   sgn = ((int)nf & 1) << 31;
    float r = __fmaf_rn(-nf, 3.140625f, x);
    r = __fmaf_rn(-nf, 9.670257568359375e-4f, r);
    r = __fmaf_rn(-nf, 6.2771141529083252e-7f, r);
    float r2 = __fmul_rn(r, r);
    float ps = __fmaf_rn(2.60831598097865935e-06f, r2, -1.98106907191686332e-4f);
    ps = __fmaf_rn(ps, r2,  8.33307858556509018e-3f);
    ps = __fmaf_rn(ps, r2, -0.166666597127914429f);
    float s = __fmaf_rn(__fmul_rn(r, r2), ps, r);
    float pc = __fmaf_rn(2.44331571e-5f, r2, -1.38873162e-3f);
    pc = __fmaf_rn(pc, r2, 4.16666456e-2f);
    pc = __fmaf_rn(pc, r2, -0.5f);
    float c = __fmaf_rn(pc, r2, 1.0f);
    so = __int_as_float(__float_as_int(s) ^ sgn);
    co = __int_as_float(__float_as_int(c) ^ sgn);
}

__device__ __forceinline__ double softplus_d(double x) {
    return (x > 0.0) ? x + log1p(exp(-x)) : log1p(exp(x));
}
__device__ __forceinline__ float sigmoid_of(float argf) {
    return (float)(1.0 / (1.0 + exp(-(double)argf)));
}

// ---------------------------------------------------------------------------
// k0: per-mode setup (32-thread blocks so the double-precision work spreads
// over ~all SMs). Phase-critical chain in explicit f32 RN; recurrence,
// rotation, and resync coefficients in double.
// ---------------------------------------------------------------------------
__global__ void k0_setup(const float* __restrict__ mu_raw,
                         const float* __restrict__ D_raw,
                         const float* __restrict__ T0_raw,
                         const float* __restrict__ Ly_raw,
                         const float* __restrict__ xo_raw,
                         const float* __restrict__ yo_raw) {
    int m = blockIdx.x * blockDim.x + threadIdx.x;
    if (m == 0) g_maxbits = 0u;
    if (m >= NMODES) return;

    float mu  = __fadd_rn((float)softplus_d((double)*mu_raw),  1e-4f);
    float Dm  = __fadd_rn((float)softplus_d((double)*D_raw),   1e-4f);
    float T0m = __fadd_rn((float)softplus_d((double)*T0_raw),  1e-4f);

    float hLy = __fmul_rn(__fadd_rn((float)tanh((double)*Ly_raw), 1.0f), 0.5f);
    float Ly  = __fadd_rn(1.1f, __fmul_rn(2.9f, hLy));
    float hx  = __fmul_rn(__fadd_rn((float)tanh((double)*xo_raw), 1.0f), 0.5f);
    float xo  = __fadd_rn(0.49f, __fmul_rn(0.51f, hx));
    float hy  = __fmul_rn(__fadd_rn((float)tanh((double)*yo_raw), 1.0f), 0.5f);
    float yo  = __fadd_rn(__fmul_rn(0.51f, Ly), __fmul_rn(__fmul_rn(0.49f, Ly), hy));
    float yi  = __fmul_rn(0.467f, Ly);

    int mi = m / MDIM + 1;
    int nj = m % MDIM + 1;
    const float PIf = (float)M_PI;

    // phase-critical: g1 -> omega -> theta, explicit f32 RN chain
    float mf = (float)mi, nf = (float)nj;
    float t1 = __fmul_rn(mf, PIf);
    float t2 = __fdiv_rn(__fmul_rn(nf, PIf), Ly);
    float g1 = __fadd_rn(__fmul_rn(t1, t1), __fmul_rn(t2, t2));
    float om_sq = __fadd_rn(__fmul_rn(T0m, g1),
                            __fmul_rn(__fmul_rn(Dm, g1), g1));
    float omega = __fsqrt_rn(fmaxf(om_sq, 0.0f));
    float theta = __fmul_rn(omega, KF);

    const double OM2d   = 2.0 * M_PI * 500.0;
    const double DOMSQd = OM2d * OM2d;
    const double ALPHAd = 3.0 * log(10.0) / DOMSQd * (DOMSQd / 6.0);
    const double BETAd  = 3.0 * log(10.0) / DOMSQd * (1.0 / 2.0 - 1.0 / 6.0);
    float om2f  = __fmul_rn(omega, omega);
    float sigma = __fadd_rn((float)ALPHAd, __fmul_rn((float)BETAd, om2f));

    const float MAXOMf = (float)(10000.0 * 2.0 * M_PI);
    const float LOWOMf = (float)(20.0 * 2.0 * M_PI);
    float a1 = __fdiv_rn(__fsub_rn(MAXOMf, omega), 100.0f);
    float a2 = __fdiv_rn(__fsub_rn(omega, LOWOMf), 100.0f);
    float valid = __fmul_rn(sigmoid_of(a1), sigmoid_of(a2));

    double PId = (double)PIf;
    float inw = __fmul_rn((float)cos(0.335 * PId * (double)mi),
                          (float)cos((double)yi * PId * (double)nj / (double)Ly));
    float outw = __fmul_rn((float)cos((double)xo * PId * (double)mi),
                           (float)cos((double)yo * PId * (double)nj / (double)Ly));

    float ms = __fmul_rn(__fmul_rn(0.25f, mu), Ly);
    float E  = (float)exp(-(double)__fmul_rn(sigma, KF));
    float P  = __fmul_rn(outw, inw);
    P = __fmul_rn(P, K2F);
    P = __fmul_rn(P, E);
    P = __fdiv_rn(P, ms);
    P = __fmul_rn(P, valid);

    float coef = __fdiv_rn(P, __fadd_rn(sin_acc(theta), 1e-8f));

    // stride-32 recurrence + rotation + resync coefficients (double)
    double sd   = (double)sigma;
    double Kd   = 1.0 / 44100.0;
    double r32d = exp(-32.0 * sd * Kd);
    double Th32 = 32.0 * (double)theta;
    double c32d = cos(Th32), s32d = sin(Th32);
    float  a    = (float)(2.0 * r32d * c32d);
    float  b    = (float)(-(r32d * r32d));
    float  z1c  = (float)(r32d * c32d);
    float  z1s  = (float)(r32d * s32d);

    double r512 = exp(-512.0 * sd * Kd);
    double Th512 = 512.0 * (double)theta;
    float  Z16c = (float)(r512 * cos(Th512));
    float  Z16s = (float)(r512 * sin(Th512));

    g_P0[m] = make_float4(theta, sigma, coef, a);
    g_P1[m] = make_float4(b, z1c, z1s, Z16c);
    g_P2[m] = Z16s;
}

// ---------------------------------------------------------------------------
// k1: modal bank. Thread owns samples {base + 32j : j<32}, base = warp*1024
// + lane (stores stay coalesced). Per mode: ONE accurate sincos builds the
// complex carrier W = C*env*e^{i(t0+1)theta}; j=16 resync is an exact complex
// rotation W*Z16 (8 ops) instead of a fresh sincos. Recurrence blocks <= 16
// steps => same error class as round 3. Scalar math (f32x2 proven parity).
// ---------------------------------------------------------------------------
__global__ void __launch_bounds__(32 * WPB) k1_bank(int T) {
    int gtid   = blockIdx.x * blockDim.x + threadIdx.x;
    int warp_t = gtid >> 5;
    int lane   = threadIdx.x & 31;
    int base   = warp_t * SPAN + lane;
    if (base >= T) return;
    int c = blockIdx.y;

    float acc[TW];
#pragma unroll
    for (int j = 0; j < TW; ++j) acc[j] = 0.0f;

    float tp0 = (float)(base + 1);
    float nk0 = __fmul_rn((float)base, KF);

    int m0 = c * CHUNK;

    // prefetch mode 0
    float4 nP0 = g_P0[m0];
    float4 nP1 = g_P1[m0];
    float  nP2 = g_P2[m0];

    for (int q = 0; q < CHUNK; ++q) {
        float4 p0 = nP0; float4 p1 = nP1; float p2 = nP2;
        if (q + 1 < CHUNK) {
            nP0 = g_P0[m0 + q + 1];
            nP1 = g_P1[m0 + q + 1];
            nP2 = g_P2[m0 + q + 1];
        }
        float th = p0.x, sg = p0.y, C = p0.z, a = p0.w;
        float b = p1.x, z1c = p1.y, z1s = p1.z, Z16c = p1.w, Z16s = p2;

        // ---- init: one accurate sincos + envelope ----
        float s0, c0;
        sincos_acc(__fmul_rn(tp0, th), s0, c0);
        float E   = __fmul_rn(C, __expf(-__fmul_rn(sg, nk0)));
        float Wim = __fmul_rn(E, s0);
        float Wre = __fmul_rn(E, c0);

        float v0 = Wim;
        float v1 = __fmaf_rn(Wre, z1s, __fmul_rn(Wim, z1c));
        acc[0] = __fadd_rn(acc[0], v0);
        acc[1] = __fadd_rn(acc[1], v1);
#pragma unroll
        for (int j = 2; j < 16; ++j) {
            float v2 = __fmaf_rn(a, v1, __fmul_rn(b, v0));
            acc[j] = __fadd_rn(acc[j], v2);
            v0 = v1; v1 = v2;
        }

        // ---- exact resync at j=16: W <- W * Z16 ----
        float Wre2 = __fmaf_rn(Wre, Z16c, -__fmul_rn(Wim, Z16s));
        float Wim2 = __fmaf_rn(Wim, Z16c,  __fmul_rn(Wre, Z16s));
        v0 = Wim2;
        v1 = __fmaf_rn(Wre2, z1s, __fmul_rn(Wim2, z1c));
        acc[16] = __fadd_rn(acc[16], v0);
        acc[17] = __fadd_rn(acc[17], v1);
#pragma unroll
        for (int j = 18; j < TW; ++j) {
            float v2 = __fmaf_rn(a, v1, __fmul_rn(b, v0));
            acc[j] = __fadd_rn(acc[j], v2);
            v0 = v1; v1 = v2;
        }
    }

#pragma unroll
    for (int j = 0; j < TW; ++j) {
        int t = base + 32 * j;
        if (t < T) g_part[c][t] = acc[j];
    }
}

// ---------------------------------------------------------------------------
// k2: sum chunks, first difference / K, track max|ir|
// ---------------------------------------------------------------------------
__global__ void k2_diff(int T) {
    __shared__ float sm[257];
    int t = blockIdx.x * blockDim.x + threadIdx.x;

    float s = 0.0f;
    if (t < T) {
#pragma unroll 8
        for (int c = 0; c < NCHUNK; ++c) s += g_part[c][t];
    }
    sm[threadIdx.x + 1] = s;
    if (threadIdx.x == 0) {
        float p = 0.0f;
        int tp = (int)(blockIdx.x * blockDim.x) - 1;
        if (tp >= 0 && tp < T) {
            for (int c = 0; c < NCHUNK; ++c) p += g_part[c][tp];
        }
        sm[0] = p;
    }
    __syncthreads();
    if (t >= T) return;

    float prev = (t == 0) ? 0.0f : sm[threadIdx.x];
    float ir = __fdiv_rn(__fsub_rn(s, prev), KF);
    g_ir[t] = ir;
    atomicMax(&g_maxbits, __float_as_uint(fabsf(ir)));
}

// ---------------------------------------------------------------------------
// k3: peak normalize
// ---------------------------------------------------------------------------
__global__ void k3_norm(int T, float* __restrict__ out) {
    int t = blockIdx.x * blockDim.x + threadIdx.x;
    if (t >= T) return;
    float mx = __uint_as_float(g_maxbits);
    out[t] = __fdiv_rn(g_ir[t], __fadd_rn(mx, 1e-8f));
}

// ---------------------------------------------------------------------------
extern "C" void kernel_launch(void* const* d_in, const int* in_sizes, int n_in,
                              void* d_out, int out_size) {
    (void)in_sizes; (void)n_in;
    const float* mu   = (const float*)d_in[0];
    const float* Dr   = (const float*)d_in[1];
    const float* T0r  = (const float*)d_in[2];
    const float* Lyr  = (const float*)d_in[3];
    const float* xor_ = (const float*)d_in[4];
    const float* yor_ = (const float*)d_in[5];

    int T = out_size;
    if (T > MAX_T) T = MAX_T;

    k0_setup<<<NMODES / 32, 32>>>(mu, Dr, T0r, Lyr, xor_, yor_);

    int warps_t  = (T + SPAN - 1) / SPAN;
    int blocks_x = (warps_t + WPB - 1) / WPB;
    dim3 g1(blocks_x, NCHUNK);
    k1_bank<<<g1, 32 * WPB>>>(T);

    int gb = (T + 255) / 256;
    k2_diff<<<gb, 256>>>(T);
    k3_norm<<<gb, 256>>>(T, (float*)d_out);
}